// round 3
// baseline (speedup 1.0000x reference)
#include <cuda_runtime.h>
#include <math.h>

// Problem dims
#define Bb   256
#define Ss   512
#define Hh   256
#define OUTD 3
#define NST  64
#define INW  259
#define G4   (4*Hh)
#define NSLICE 4
#define SLROWS (Ss/NSLICE)   // 128

// Output layout
#define OFF_PRED 0
#define OFF_HID  (Bb*NST*OUTD)          // 49152
#define OFF_ATT  (OFF_HID + Bb*Hh)      // 114688

// Persistent device state
__device__ float g_h[Bb*Hh];
__device__ float g_c[Bb*Hh];
__device__ float g_x[Bb*OUTD];
__device__ float g_v[Bb*Hh];
__device__ float g_gates[Bb*G4];
__device__ float g_Wcat[G4*512];
__device__ float g_Wx[G4*OUTD];
__device__ float g_bias[G4];
__device__ float g_M[Hh*Hh];       // M[k*256+j] = sum_g Wa[g,k]*Ua[g,j]
__device__ float g_vb[Hh];         // vb[j] = sum_g ba[g]*Ua[g,j]
__device__ float g_pm[Bb*NSLICE];
__device__ float g_pl[Bb*NSLICE];
__device__ float g_pctx[Bb*NSLICE*Hh];

__device__ __forceinline__ float warp_sum(float v){
  #pragma unroll
  for (int o = 16; o; o >>= 1) v += __shfl_xor_sync(0xffffffffu, v, o);
  return v;
}
__device__ __forceinline__ float sigmoidf_(float x){ return 1.f/(1.f+expf(-x)); }

// ---------------------------------------------------------------- init/pack/prep
__global__ void k_init(const float* __restrict__ eh, const float* __restrict__ ec){
  int i = blockIdx.x*blockDim.x + threadIdx.x;
  if (i < Bb*Hh){ g_h[i] = eh[i]; g_c[i] = ec[i]; }
  if (i < Bb*OUTD) g_x[i] = 0.f;
}

__global__ void k_pack(const float* __restrict__ Wih, const float* __restrict__ Whh,
                       const float* __restrict__ bih, const float* __restrict__ bhh){
  int j = blockIdx.x, k = threadIdx.x;
  g_Wcat[j*512 + k] = (k < Hh) ? Wih[j*INW + OUTD + k] : Whh[j*Hh + (k - Hh)];
  if (k < OUTD) g_Wx[j*OUTD + k] = Wih[j*INW + k];
  if (k == 0)   g_bias[j] = bih[j] + bhh[j];
}

// M = Wa^T @ Ua ; vb = ba @ Ua
__global__ void k_prep(const float* __restrict__ Wa, const float* __restrict__ ba,
                       const float* __restrict__ Ua){
  int kk = blockIdx.x, j = threadIdx.x;
  float a = 0.f;
  if (kk < Hh){
    #pragma unroll 4
    for (int g = 0; g < Hh; g++) a = fmaf(Wa[g*Hh + kk], Ua[g*Hh + j], a);
    g_M[kk*Hh + j] = a;
  } else {
    #pragma unroll 4
    for (int g = 0; g < Hh; g++) a = fmaf(ba[g], Ua[g*Hh + j], a);
    g_vb[j] = a;
  }
}

// initial v from h0: one block per batch
__global__ void k_v0(){
  __shared__ float h_s[Hh];
  int b = blockIdx.x, tid = threadIdx.x;
  h_s[tid] = g_h[b*Hh + tid];
  __syncthreads();
  float acc = 0.f;
  #pragma unroll 8
  for (int k = 0; k < Hh; k++) acc = fmaf(h_s[k], g_M[k*Hh + tid], acc);
  g_v[b*Hh + tid] = acc + g_vb[tid];
}

// ---------------------------------------------------------------- attention (single-pass, sliced)
__global__ void k_attn(const float* __restrict__ enc, float* __restrict__ out, int t){
  __shared__ float tile[32][Hh];
  __shared__ float v_s[Hh];
  __shared__ float ctx_s[Hh];
  __shared__ float tsc[32];
  __shared__ float wbuf[SLROWS];
  __shared__ float tmaxs[4];
  __shared__ float red0;
  int slice = blockIdx.x, b = blockIdx.y;
  int tid = threadIdx.x, wid = tid >> 5, lane = tid & 31;
  int s0 = slice * SLROWS;
  const float* encb = enc + (size_t)b*Ss*Hh;

  v_s[tid] = g_v[b*Hh + tid];
  ctx_s[tid] = 0.f;
  float m_run = -3.0e38f, l_run = 0.f;
  __syncthreads();

  for (int ti = 0; ti < 4; ti++){
    const float4* src = (const float4*)(encb + (size_t)(s0 + ti*32)*Hh);
    float4* dst = (float4*)&tile[0][0];
    #pragma unroll
    for (int i = 0; i < 8; i++) dst[tid + 256*i] = src[tid + 256*i];
    __syncthreads();

    #pragma unroll
    for (int r = 0; r < 4; r++){
      int s = wid*4 + r;
      float acc = 0.f;
      #pragma unroll
      for (int k = 0; k < 8; k++) acc = fmaf(tile[s][lane + 32*k], v_s[lane + 32*k], acc);
      acc = warp_sum(acc);
      if (!lane) tsc[s] = acc;
    }
    __syncthreads();

    float mt = tsc[0];
    #pragma unroll
    for (int s = 1; s < 32; s++) mt = fmaxf(mt, tsc[s]);
    float m_new = fmaxf(m_run, mt);
    float scale = expf(m_run - m_new);

    if (wid == 0){
      float e = expf(tsc[lane] - m_new);
      wbuf[ti*32 + lane] = e;
      float es = warp_sum(e);
      if (!lane){ red0 = es; tmaxs[ti] = m_new; }
    }
    __syncthreads();
    l_run = l_run * scale + red0;
    m_run = m_new;

    float c = ctx_s[tid] * scale;
    #pragma unroll
    for (int s = 0; s < 32; s++) c = fmaf(wbuf[ti*32 + s], tile[s][tid], c);
    ctx_s[tid] = c;
    __syncthreads();
  }

  g_pctx[(b*NSLICE + slice)*Hh + tid] = ctx_s[tid];
  if (tid < SLROWS){
    float e = wbuf[tid] * expf(tmaxs[tid >> 5] - m_run);
    out[OFF_ATT + ((size_t)b*NST + t)*Ss + s0 + tid] = e;  // unnormalized; rescaled in k_lstm
  }
  if (tid == 0){
    g_pm[b*NSLICE + slice] = m_run;
    g_pl[b*NSLICE + slice] = l_run;
  }
}

// ---------------------------------------------------------------- gates GEMM (with fused ctx combine)
#define BM 32
#define BN 64
#define BK 32
__global__ void k_gates(){
  __shared__ float As[BK][BM + 4];   // row stride 36 floats = 144B (16B-aligned)
  __shared__ float Bs[BK][BN + 4];   // 68 floats = 272B (16B-aligned)
  __shared__ float fs_s[BM][4];
  int tid = threadIdx.x;             // 128
  int n0 = blockIdx.x * BN, m0 = blockIdx.y * BM;

  // prologue: per-row combine factors fs = exp(m_s - M)/L
  if (tid < BM){
    int b = m0 + tid;
    float m0v = g_pm[b*4+0], m1 = g_pm[b*4+1], m2 = g_pm[b*4+2], m3 = g_pm[b*4+3];
    float Mx = fmaxf(fmaxf(m0v, m1), fmaxf(m2, m3));
    float f0 = expf(m0v-Mx), f1 = expf(m1-Mx), f2 = expf(m2-Mx), f3 = expf(m3-Mx);
    float L = g_pl[b*4+0]*f0 + g_pl[b*4+1]*f1 + g_pl[b*4+2]*f2 + g_pl[b*4+3]*f3;
    float inv = 1.f / L;
    fs_s[tid][0] = f0*inv; fs_s[tid][1] = f1*inv;
    fs_s[tid][2] = f2*inv; fs_s[tid][3] = f3*inv;
  }
  __syncthreads();

  int tx = tid & 15, ty = tid >> 4;  // tx: n (x4), ty: m (x4)
  float acc[4][4] = {};

  for (int kt = 0; kt < 512; kt += BK){
    // A tile: BM x BK (1024 floats = 256 float4, 2 per thread)
    #pragma unroll
    for (int i = 0; i < 2; i++){
      int idx = tid + 128*i;
      int rr = idx >> 3, c4 = (idx & 7) << 2;
      int b = m0 + rr;
      float4 a4;
      if (kt < Hh){
        const float* p = g_pctx + (size_t)(b*NSLICE)*Hh + kt + c4;
        float4 p0 = *(const float4*)(p);
        float4 p1 = *(const float4*)(p + Hh);
        float4 p2 = *(const float4*)(p + 2*Hh);
        float4 p3 = *(const float4*)(p + 3*Hh);
        float f0 = fs_s[rr][0], f1 = fs_s[rr][1], f2 = fs_s[rr][2], f3 = fs_s[rr][3];
        a4.x = p0.x*f0 + p1.x*f1 + p2.x*f2 + p3.x*f3;
        a4.y = p0.y*f0 + p1.y*f1 + p2.y*f2 + p3.y*f3;
        a4.z = p0.z*f0 + p1.z*f1 + p2.z*f2 + p3.z*f3;
        a4.w = p0.w*f0 + p1.w*f1 + p2.w*f2 + p3.w*f3;
      } else {
        a4 = *(const float4*)(g_h + b*Hh + (kt - Hh) + c4);
      }
      As[c4+0][rr] = a4.x; As[c4+1][rr] = a4.y;
      As[c4+2][rr] = a4.z; As[c4+3][rr] = a4.w;
    }
    // B tile: BN x BK (2048 floats = 512 float4, 4 per thread)
    #pragma unroll
    for (int i = 0; i < 4; i++){
      int idx = tid + 128*i;
      int nrow = idx >> 3, c4 = (idx & 7) << 2;
      float4 b4 = *(const float4*)(g_Wcat + (size_t)(n0 + nrow)*512 + kt + c4);
      Bs[c4+0][nrow] = b4.x; Bs[c4+1][nrow] = b4.y;
      Bs[c4+2][nrow] = b4.z; Bs[c4+3][nrow] = b4.w;
    }
    __syncthreads();
    #pragma unroll
    for (int kk = 0; kk < BK; kk++){
      float4 a4 = *(const float4*)(&As[kk][ty*4]);
      float4 b4 = *(const float4*)(&Bs[kk][tx*4]);
      float av[4] = {a4.x, a4.y, a4.z, a4.w};
      float bv[4] = {b4.x, b4.y, b4.z, b4.w};
      #pragma unroll
      for (int i = 0; i < 4; i++)
        #pragma unroll
        for (int j = 0; j < 4; j++)
          acc[i][j] = fmaf(av[i], bv[j], acc[i][j]);
    }
    __syncthreads();
  }

  #pragma unroll
  for (int i = 0; i < 4; i++){
    int bidx = m0 + ty*4 + i;
    float x0 = g_x[bidx*OUTD+0], x1 = g_x[bidx*OUTD+1], x2 = g_x[bidx*OUTD+2];
    #pragma unroll
    for (int j = 0; j < 4; j++){
      int n = n0 + tx*4 + j;
      g_gates[(size_t)bidx*G4 + n] = acc[i][j] + g_bias[n]
        + x0*g_Wx[n*OUTD+0] + x1*g_Wx[n*OUTD+1] + x2*g_Wx[n*OUTD+2];
    }
  }
}

// ---------------------------------------------------------------- LSTM + pred + att rescale + next v
__global__ void k_lstm(const float* __restrict__ Wo, const float* __restrict__ bo,
                       float* __restrict__ out, int t){
  __shared__ float h_s[Hh];
  __shared__ float fs_b[4];
  int b = blockIdx.x, tid = threadIdx.x, wid = tid >> 5, lane = tid & 31;

  // combine factors for this batch (all threads compute; cheap)
  {
    float m0v = g_pm[b*4+0], m1 = g_pm[b*4+1], m2 = g_pm[b*4+2], m3 = g_pm[b*4+3];
    float Mx = fmaxf(fmaxf(m0v, m1), fmaxf(m2, m3));
    float f0 = expf(m0v-Mx), f1 = expf(m1-Mx), f2 = expf(m2-Mx), f3 = expf(m3-Mx);
    float L = g_pl[b*4+0]*f0 + g_pl[b*4+1]*f1 + g_pl[b*4+2]*f2 + g_pl[b*4+3]*f3;
    float inv = 1.f / L;
    if (tid < 4){
      float fv[4] = {f0, f1, f2, f3};
      fs_b[tid] = fv[tid] * inv;
    }
  }

  const float* gb = g_gates + (size_t)b*G4;
  float gi = gb[tid], gf = gb[Hh + tid], gg = gb[2*Hh + tid], go = gb[3*Hh + tid];
  float c  = g_c[b*Hh + tid];
  float cn = sigmoidf_(gf)*c + sigmoidf_(gi)*tanhf(gg);
  float hn = sigmoidf_(go)*tanhf(cn);
  g_c[b*Hh + tid] = cn;
  g_h[b*Hh + tid] = hn;
  h_s[tid] = hn;
  if (t == NST-1) out[OFF_HID + b*Hh + tid] = hn;
  __syncthreads();

  // rescale attention weights in place
  {
    float* att = out + OFF_ATT + ((size_t)b*NST + t)*Ss;
    att[tid]       *= fs_b[tid >> 7];
    att[tid + 256] *= fs_b[(tid + 256) >> 7];
  }

  // prediction (warps 0..2)
  if (wid < 3){
    float a = 0.f;
    #pragma unroll
    for (int k = lane; k < Hh; k += 32) a = fmaf(h_s[k], Wo[wid*Hh + k], a);
    a = warp_sum(a);
    if (!lane){
      float p = a + bo[wid];
      out[OFF_PRED + ((size_t)b*NST + t)*OUTD + wid] = p;
      g_x[b*OUTD + wid] = p;
    }
  }

  // next step's v = h_new @ M + vb
  if (t != NST-1){
    float acc = 0.f;
    #pragma unroll 8
    for (int k = 0; k < Hh; k++) acc = fmaf(h_s[k], g_M[k*Hh + tid], acc);
    g_v[b*Hh + tid] = acc + g_vb[tid];
  }
}

// ---------------------------------------------------------------- launch
extern "C" void kernel_launch(void* const* d_in, const int* in_sizes, int n_in,
                              void* d_out, int out_size){
  const float* enc  = (const float*)d_in[0];
  const float* ehid = (const float*)d_in[1];
  const float* ecell= (const float*)d_in[2];
  const float* Wa   = (const float*)d_in[3];
  const float* ba   = (const float*)d_in[4];
  const float* Ua   = (const float*)d_in[5];
  /* d_in[6] (bua): softmax-invariant, unused */
  const float* Wih  = (const float*)d_in[7];
  const float* Whh  = (const float*)d_in[8];
  const float* bih  = (const float*)d_in[9];
  const float* bhh  = (const float*)d_in[10];
  const float* Wo   = (const float*)d_in[11];
  const float* bo   = (const float*)d_in[12];
  float* out = (float*)d_out;

  k_init<<<256, 256>>>(ehid, ecell);
  k_pack<<<G4, 512>>>(Wih, Whh, bih, bhh);
  k_prep<<<Hh + 1, 256>>>(Wa, ba, Ua);
  k_v0<<<Bb, 256>>>();
  for (int t = 0; t < NST; t++){
    k_attn<<<dim3(NSLICE, Bb), 256>>>(enc, out, t);
    k_gates<<<dim3(G4/BN, Bb/BM), 128>>>();
    k_lstm<<<Bb, 256>>>(Wo, bo, out, t);
  }
}

// round 6
// speedup vs baseline: 1.3150x; 1.3150x over previous
#include <cuda_runtime.h>
#include <math.h>
#include <stdint.h>

// Problem dims
#define Bb   256
#define Ss   512
#define Hh   256
#define OUTD 3
#define NST  64
#define INW  259
#define G4   (4*Hh)
#define NSLICE 4
#define SLROWS (Ss/NSLICE)   // 128

// Output layout
#define OFF_PRED 0
#define OFF_HID  (Bb*NST*OUTD)          // 49152
#define OFF_ATT  (OFF_HID + Bb*Hh)      // 114688

// Persistent device state
__device__ float g_h[Bb*Hh];
__device__ float g_c[Bb*Hh];
__device__ float g_x[Bb*OUTD];
__device__ float g_v[Bb*Hh];
__device__ float g_gates[Bb*G4];
__device__ float g_WcatT[512*G4];  // [k][n]: k<256 -> ctx weights, else h weights
__device__ float g_Wx[G4*OUTD];
__device__ float g_bias[G4];
__device__ float g_M[Hh*Hh];       // M[k*256+j] = sum_g Wa[g,k]*Ua[g,j]
__device__ float g_vb[Hh];
__device__ float g_pm[Bb*NSLICE];
__device__ float g_pl[Bb*NSLICE];
__device__ float g_pctx[Bb*NSLICE*Hh];

__device__ __forceinline__ float warp_sum(float v){
  #pragma unroll
  for (int o = 16; o; o >>= 1) v += __shfl_xor_sync(0xffffffffu, v, o);
  return v;
}
__device__ __forceinline__ float sigmoidf_(float x){ return 1.f/(1.f+expf(-x)); }

// cp.async helpers
__device__ __forceinline__ uint32_t smem_u32(const void* p){
  return (uint32_t)__cvta_generic_to_shared(p);
}
__device__ __forceinline__ void cp16(uint32_t dst, const void* src){
  asm volatile("cp.async.cg.shared.global [%0], [%1], 16;" :: "r"(dst), "l"(src));
}
#define CP_COMMIT() asm volatile("cp.async.commit_group;")
#define CP_WAIT(n)  asm volatile("cp.async.wait_group %0;" :: "n"(n))

// packed f32x2 fma (Blackwell)
__device__ __forceinline__ void fma2(unsigned long long &d, unsigned long long a, unsigned long long b){
  asm("fma.rn.f32x2 %0, %1, %2, %3;" : "=l"(d) : "l"(a), "l"(b), "l"(d));
}
__device__ __forceinline__ unsigned long long dup2(float v){
  unsigned long long r; uint32_t u = __float_as_uint(v);
  asm("mov.b64 %0, {%1, %1};" : "=l"(r) : "r"(u));
  return r;
}
__device__ __forceinline__ float2 unpack2(unsigned long long v){
  uint32_t lo, hi;
  asm("mov.b64 {%0, %1}, %2;" : "=r"(lo), "=r"(hi) : "l"(v));
  return make_float2(__uint_as_float(lo), __uint_as_float(hi));
}

// ---------------------------------------------------------------- init/pack/prep
__global__ void k_init(const float* __restrict__ eh, const float* __restrict__ ec){
  int i = blockIdx.x*blockDim.x + threadIdx.x;
  if (i < Bb*Hh){ g_h[i] = eh[i]; g_c[i] = ec[i]; }
  if (i < Bb*OUTD) g_x[i] = 0.f;
}

__global__ void k_pack(const float* __restrict__ Wih, const float* __restrict__ Whh,
                       const float* __restrict__ bih, const float* __restrict__ bhh){
  int j = blockIdx.x;   // 0..1023 (n)
  int k = threadIdx.x;  // 0..511
  float val = (k < Hh) ? Wih[j*INW + OUTD + k] : Whh[j*Hh + (k - Hh)];
  g_WcatT[(size_t)k*G4 + j] = val;
  if (k < OUTD) g_Wx[j*OUTD + k] = Wih[j*INW + k];
  if (k == 0)   g_bias[j] = bih[j] + bhh[j];
}

__global__ void k_prep(const float* __restrict__ Wa, const float* __restrict__ ba,
                       const float* __restrict__ Ua){
  int kk = blockIdx.x, j = threadIdx.x;
  float a = 0.f;
  if (kk < Hh){
    #pragma unroll 4
    for (int g = 0; g < Hh; g++) a = fmaf(Wa[g*Hh + kk], Ua[g*Hh + j], a);
    g_M[kk*Hh + j] = a;
  } else {
    #pragma unroll 4
    for (int g = 0; g < Hh; g++) a = fmaf(ba[g], Ua[g*Hh + j], a);
    g_vb[j] = a;
  }
}

// ---------------------------------------------------------------- attention (cp.async pipelined flash)
#define TR 16
__global__ void k_attn(const float* __restrict__ enc, float* __restrict__ out, int t){
  __shared__ float buf[2][TR][Hh];    // 32 KB
  __shared__ float v_s[Hh];
  __shared__ float ctx_s[Hh];
  __shared__ float tsc[TR];
  __shared__ float wbuf[SLROWS];
  __shared__ float tmaxs[8];
  __shared__ float red0;
  int slice = blockIdx.x, b = blockIdx.y;
  int tid = threadIdx.x, wid = tid >> 5, lane = tid & 31;
  int s0 = slice * SLROWS;
  const float* encb = enc + (size_t)b*Ss*Hh;

  v_s[tid] = g_v[b*Hh + tid];
  ctx_s[tid] = 0.f;
  float m_run = -3.0e38f, l_run = 0.f;

  // prefetch tile 0
  {
    const float4* src = (const float4*)(encb + (size_t)s0*Hh);
    uint32_t dst = smem_u32(&buf[0][0][0]);
    #pragma unroll
    for (int i = 0; i < 4; i++){
      int idx = tid + 256*i;
      cp16(dst + idx*16, src + idx);
    }
    CP_COMMIT();
  }
  __syncthreads();   // v_s/ctx_s visible

  for (int ti = 0; ti < 8; ti++){
    if (ti < 7){
      const float4* src = (const float4*)(encb + (size_t)(s0 + (ti+1)*TR)*Hh);
      uint32_t dst = smem_u32(&buf[(ti+1)&1][0][0]);
      #pragma unroll
      for (int i = 0; i < 4; i++){
        int idx = tid + 256*i;
        cp16(dst + idx*16, src + idx);
      }
      CP_COMMIT();
      CP_WAIT(1);
    } else {
      CP_WAIT(0);
    }
    __syncthreads();
    float (*tile)[Hh] = buf[ti&1];

    // scores: 2 rows per warp
    #pragma unroll
    for (int r = 0; r < 2; r++){
      int s = wid*2 + r;
      float acc = 0.f;
      #pragma unroll
      for (int k = 0; k < 8; k++) acc = fmaf(tile[s][lane + 32*k], v_s[lane + 32*k], acc);
      acc = warp_sum(acc);
      if (!lane) tsc[s] = acc;
    }
    __syncthreads();

    float mt = tsc[0];
    #pragma unroll
    for (int s = 1; s < TR; s++) mt = fmaxf(mt, tsc[s]);
    float m_new = fmaxf(m_run, mt);
    float scale = expf(m_run - m_new);

    if (wid == 0){
      float e = (lane < TR) ? expf(tsc[lane] - m_new) : 0.f;
      if (lane < TR) wbuf[ti*TR + lane] = e;
      float es = warp_sum(e);
      if (!lane){ red0 = es; tmaxs[ti] = m_new; }
    }
    __syncthreads();
    l_run = l_run * scale + red0;
    m_run = m_new;

    float c = ctx_s[tid] * scale;
    #pragma unroll
    for (int s = 0; s < TR; s++) c = fmaf(wbuf[ti*TR + s], tile[s][tid], c);
    ctx_s[tid] = c;
    __syncthreads();
  }

  g_pctx[(b*NSLICE + slice)*Hh + tid] = ctx_s[tid];
  if (tid < SLROWS){
    float e = wbuf[tid] * expf(tmaxs[tid >> 4] - m_run);
    out[OFF_ATT + ((size_t)b*NST + t)*Ss + s0 + tid] = e;  // rescaled in k_lstm
  }
  if (tid == 0){
    g_pm[b*NSLICE + slice] = m_run;
    g_pl[b*NSLICE + slice] = l_run;
  }
}

// ---------------------------------------------------------------- gates GEMM (cp.async + f32x2)
#define BM 32
#define BN 64
#define KT 32
__global__ void k_gates(){
  __shared__ float As[2][KT][BM + 4];      // [k][m]
  __shared__ float Bs[2][KT][BN + 4];      // [k][n]
  __shared__ float fs_s[BM][4];
  int tid = threadIdx.x;                    // 128
  int n0 = blockIdx.x * BN, m0 = blockIdx.y * BM;

  if (tid < BM){
    int b = m0 + tid;
    float m0v = g_pm[b*4+0], m1 = g_pm[b*4+1], m2 = g_pm[b*4+2], m3 = g_pm[b*4+3];
    float Mx = fmaxf(fmaxf(m0v, m1), fmaxf(m2, m3));
    float f0 = expf(m0v-Mx), f1 = expf(m1-Mx), f2 = expf(m2-Mx), f3 = expf(m3-Mx);
    float L = g_pl[b*4+0]*f0 + g_pl[b*4+1]*f1 + g_pl[b*4+2]*f2 + g_pl[b*4+3]*f3;
    float inv = 1.f / L;
    fs_s[tid][0] = f0*inv; fs_s[tid][1] = f1*inv;
    fs_s[tid][2] = f2*inv; fs_s[tid][3] = f3*inv;
  }
  __syncthreads();

  int tx = tid & 15, ty = tid >> 4;  // tx: n(x4), ty: m(x4)
  unsigned long long acc2[4][2] = {};

  // loaders
  auto loadB = [&](int it){
    int kt = it*KT, pb = it & 1;
    #pragma unroll
    for (int i = 0; i < 4; i++){
      int idx = tid + 128*i;            // 512 float4
      int row = idx >> 4, col4 = idx & 15;
      cp16(smem_u32(&Bs[pb][row][col4*4]),
           g_WcatT + (size_t)(kt + row)*G4 + n0 + col4*4);
    }
    CP_COMMIT();
  };
  auto loadA = [&](int it){
    int kt = it*KT, pb = it & 1;
    #pragma unroll
    for (int i = 0; i < 2; i++){
      int idx = tid + 128*i;            // 256 float4
      int rr = idx >> 3, c4 = (idx & 7) << 2;
      int b = m0 + rr;
      float4 a4;
      if (kt < Hh){
        const float* p = g_pctx + (size_t)(b*NSLICE)*Hh + kt + c4;
        float4 p0 = *(const float4*)(p);
        float4 p1 = *(const float4*)(p + Hh);
        float4 p2 = *(const float4*)(p + 2*Hh);
        float4 p3 = *(const float4*)(p + 3*Hh);
        float f0 = fs_s[rr][0], f1 = fs_s[rr][1], f2 = fs_s[rr][2], f3 = fs_s[rr][3];
        a4.x = p0.x*f0 + p1.x*f1 + p2.x*f2 + p3.x*f3;
        a4.y = p0.y*f0 + p1.y*f1 + p2.y*f2 + p3.y*f3;
        a4.z = p0.z*f0 + p1.z*f1 + p2.z*f2 + p3.z*f3;
        a4.w = p0.w*f0 + p1.w*f1 + p2.w*f2 + p3.w*f3;
      } else {
        a4 = *(const float4*)(g_h + b*Hh + (kt - Hh) + c4);
      }
      As[pb][c4+0][rr] = a4.x; As[pb][c4+1][rr] = a4.y;
      As[pb][c4+2][rr] = a4.z; As[pb][c4+3][rr] = a4.w;
    }
  };

  loadB(0); loadA(0);
  for (int it = 0; it < 16; it++){
    if (it < 15){ loadB(it+1); loadA(it+1); CP_WAIT(1); }
    else        { CP_WAIT(0); }
    __syncthreads();
    int pb = it & 1;
    #pragma unroll
    for (int kk = 0; kk < KT; kk++){
      float4 a4 = *(const float4*)(&As[pb][kk][ty*4]);
      const unsigned long long* bp = (const unsigned long long*)(&Bs[pb][kk][tx*4]);
      unsigned long long b0 = bp[0], b1 = bp[1];
      unsigned long long d0 = dup2(a4.x), d1 = dup2(a4.y), d2 = dup2(a4.z), d3 = dup2(a4.w);
      fma2(acc2[0][0], d0, b0); fma2(acc2[0][1], d0, b1);
      fma2(acc2[1][0], d1, b0); fma2(acc2[1][1], d1, b1);
      fma2(acc2[2][0], d2, b0); fma2(acc2[2][1], d2, b1);
      fma2(acc2[3][0], d3, b0); fma2(acc2[3][1], d3, b1);
    }
    __syncthreads();
  }

  #pragma unroll
  for (int i = 0; i < 4; i++){
    int bidx = m0 + ty*4 + i;
    float x0 = g_x[bidx*OUTD+0], x1 = g_x[bidx*OUTD+1], x2 = g_x[bidx*OUTD+2];
    float2 v0 = unpack2(acc2[i][0]), v1 = unpack2(acc2[i][1]);
    float av[4] = {v0.x, v0.y, v1.x, v1.y};
    #pragma unroll
    for (int j = 0; j < 4; j++){
      int n = n0 + tx*4 + j;
      g_gates[(size_t)bidx*G4 + n] = av[j] + g_bias[n]
        + x0*g_Wx[n*OUTD+0] + x1*g_Wx[n*OUTD+1] + x2*g_Wx[n*OUTD+2];
    }
  }
}

// ---------------------------------------------------------------- v GEMM: v = h@M + vb (pipelined)
__global__ void k_v(){
  __shared__ float As[2][KT][BM + 4];
  __shared__ float Bs[2][KT][BN + 4];
  int tid = threadIdx.x;                    // 128
  int n0 = blockIdx.x * BN, m0 = blockIdx.y * BM;
  int tx = tid & 15, ty = tid >> 4;
  unsigned long long acc2[4][2] = {};

  auto loadB = [&](int it){
    int kt = it*KT, pb = it & 1;
    #pragma unroll
    for (int i = 0; i < 4; i++){
      int idx = tid + 128*i;
      int row = idx >> 4, col4 = idx & 15;
      cp16(smem_u32(&Bs[pb][row][col4*4]),
           g_M + (size_t)(kt + row)*Hh + n0 + col4*4);
    }
    CP_COMMIT();
  };
  auto loadA = [&](int it){
    int kt = it*KT, pb = it & 1;
    #pragma unroll
    for (int i = 0; i < 2; i++){
      int idx = tid + 128*i;
      int rr = idx >> 3, c4 = (idx & 7) << 2;
      float4 a4 = *(const float4*)(g_h + (m0 + rr)*Hh + kt + c4);
      As[pb][c4+0][rr] = a4.x; As[pb][c4+1][rr] = a4.y;
      As[pb][c4+2][rr] = a4.z; As[pb][c4+3][rr] = a4.w;
    }
  };

  loadB(0); loadA(0);
  for (int it = 0; it < 8; it++){
    if (it < 7){ loadB(it+1); loadA(it+1); CP_WAIT(1); }
    else       { CP_WAIT(0); }
    __syncthreads();
    int pb = it & 1;
    #pragma unroll
    for (int kk = 0; kk < KT; kk++){
      float4 a4 = *(const float4*)(&As[pb][kk][ty*4]);
      const unsigned long long* bp = (const unsigned long long*)(&Bs[pb][kk][tx*4]);
      unsigned long long b0 = bp[0], b1 = bp[1];
      unsigned long long d0 = dup2(a4.x), d1 = dup2(a4.y), d2 = dup2(a4.z), d3 = dup2(a4.w);
      fma2(acc2[0][0], d0, b0); fma2(acc2[0][1], d0, b1);
      fma2(acc2[1][0], d1, b0); fma2(acc2[1][1], d1, b1);
      fma2(acc2[2][0], d2, b0); fma2(acc2[2][1], d2, b1);
      fma2(acc2[3][0], d3, b0); fma2(acc2[3][1], d3, b1);
    }
    __syncthreads();
  }

  #pragma unroll
  for (int i = 0; i < 4; i++){
    int b = m0 + ty*4 + i;
    float2 v0 = unpack2(acc2[i][0]), v1 = unpack2(acc2[i][1]);
    float av[4] = {v0.x, v0.y, v1.x, v1.y};
    #pragma unroll
    for (int j = 0; j < 4; j++){
      int n = n0 + tx*4 + j;
      g_v[b*Hh + n] = av[j] + g_vb[n];
    }
  }
}

// ---------------------------------------------------------------- LSTM + pred + att rescale
__global__ void k_lstm(const float* __restrict__ Wo, const float* __restrict__ bo,
                       float* __restrict__ out, int t){
  __shared__ float h_s[Hh];
  __shared__ float fs_b[4];
  int b = blockIdx.x, tid = threadIdx.x, wid = tid >> 5, lane = tid & 31;

  {
    float m0v = g_pm[b*4+0], m1 = g_pm[b*4+1], m2 = g_pm[b*4+2], m3 = g_pm[b*4+3];
    float Mx = fmaxf(fmaxf(m0v, m1), fmaxf(m2, m3));
    float f0 = expf(m0v-Mx), f1 = expf(m1-Mx), f2 = expf(m2-Mx), f3 = expf(m3-Mx);
    float L = g_pl[b*4+0]*f0 + g_pl[b*4+1]*f1 + g_pl[b*4+2]*f2 + g_pl[b*4+3]*f3;
    float inv = 1.f / L;
    if (tid < 4){
      float fv[4] = {f0, f1, f2, f3};
      fs_b[tid] = fv[tid] * inv;
    }
  }

  const float* gb = g_gates + (size_t)b*G4;
  float gi = gb[tid], gf = gb[Hh + tid], gg = gb[2*Hh + tid], go = gb[3*Hh + tid];
  float c  = g_c[b*Hh + tid];
  float cn = sigmoidf_(gf)*c + sigmoidf_(gi)*tanhf(gg);
  float hn = sigmoidf_(go)*tanhf(cn);
  g_c[b*Hh + tid] = cn;
  g_h[b*Hh + tid] = hn;
  h_s[tid] = hn;
  if (t == NST-1) out[OFF_HID + b*Hh + tid] = hn;
  __syncthreads();

  {
    float* att = out + OFF_ATT + ((size_t)b*NST + t)*Ss;
    att[tid]       *= fs_b[tid >> 7];
    att[tid + 256] *= fs_b[(tid + 256) >> 7];
  }

  if (wid < 3){
    float a = 0.f;
    #pragma unroll
    for (int k = lane; k < Hh; k += 32) a = fmaf(h_s[k], Wo[wid*Hh + k], a);
    a = warp_sum(a);
    if (!lane){
      float p = a + bo[wid];
      out[OFF_PRED + ((size_t)b*NST + t)*OUTD + wid] = p;
      g_x[b*OUTD + wid] = p;
    }
  }
}

// ---------------------------------------------------------------- launch
extern "C" void kernel_launch(void* const* d_in, const int* in_sizes, int n_in,
                              void* d_out, int out_size){
  const float* enc  = (const float*)d_in[0];
  const float* ehid = (const float*)d_in[1];
  const float* ecell= (const float*)d_in[2];
  const float* Wa   = (const float*)d_in[3];
  const float* ba   = (const float*)d_in[4];
  const float* Ua   = (const float*)d_in[5];
  /* d_in[6] (bua): softmax-invariant, unused */
  const float* Wih  = (const float*)d_in[7];
  const float* Whh  = (const float*)d_in[8];
  const float* bih  = (const float*)d_in[9];
  const float* bhh  = (const float*)d_in[10];
  const float* Wo   = (const float*)d_in[11];
  const float* bo   = (const float*)d_in[12];
  float* out = (float*)d_out;

  k_init<<<256, 256>>>(ehid, ecell);
  k_pack<<<G4, 512>>>(Wih, Whh, bih, bhh);
  k_prep<<<Hh + 1, 256>>>(Wa, ba, Ua);
  k_v<<<dim3(Hh/BN, Bb/BM), 128>>>();
  for (int t = 0; t < NST; t++){
    k_attn<<<dim3(NSLICE, Bb), 256>>>(enc, out, t);
    k_gates<<<dim3(G4/BN, Bb/BM), 128>>>();
    k_lstm<<<Bb, 256>>>(Wo, bo, out, t);
    if (t != NST-1) k_v<<<dim3(Hh/BN, Bb/BM), 128>>>();
  }
}